// round 12
// baseline (speedup 1.0000x reference)
#include <cuda_runtime.h>

// Problem shapes (fixed)
#define BB 32
#define NN 4096
#define DD 8
#define NEE 2048
#define DEE 4
#define NSPLIT 4

// Device scratch (static globals; no allocation). Zero-initialized at module
// load; every kernel_launch call leaves masks zeroed again (k_compact tail),
// so the sequence is deterministic call-to-call.
__device__ unsigned g_mask_int[NN];
__device__ unsigned g_mask_ext[NEE];
__device__ long long g_list[BB][6784];   // premultiplied byte offsets rel. W_int
__device__ int g_cnt[BB];                // padded combined length (multiple of 16)
__device__ float g_part[NSPLIT][BB][NN]; // split-K partial sums
__device__ float g_zero[NN];             // stays all-zero; pad rows point here

// ---------------------------------------------------------------------------
// Kernel 1 (fused spike + mask): thread per (b,n).
// ---------------------------------------------------------------------------
__global__ void k_spikemask(const float* __restrict__ V, const float* __restrict__ a,
                            const float* __restrict__ Xd, const float* __restrict__ Xext,
                            const float* __restrict__ dmap_int,
                            const float* __restrict__ dmap_ext,
                            float* __restrict__ out) {
    int idx = blockIdx.x * blockDim.x + threadIdx.x;   // 0 .. B*N-1
    int b = idx >> 12;                                 // idx / NN
    int n = idx & (NN - 1);

    float v  = V[idx];
    float aa = a[idx];
    float th = __fadd_rn(1.0f, __fmul_rn(1.8f, aa));
    float x  = (__fadd_rn(v, -th) >= 0.0f) ? 1.0f : 0.0f;
    out[idx] = x;                                       // row 0: X
    out[2 * BB * NN + idx] = 0.98f * aa + x;            // row 2: a_new

    // internal source (b, n)
    {
        int del = 0;
#pragma unroll
        for (int d = 0; d < DD; d++)
            if (dmap_int[d * NN + n] > 0.5f) del = d;
        float xs = (del == 0) ? x : Xd[(size_t)(del - 1) * BB * NN + idx];
        if (xs > 0.5f) atomicOr(&g_mask_int[n], 1u << b);
    }
    // external source (b, n) for n < NE
    if (n < NEE) {
        int del = 0;
#pragma unroll
        for (int d = 0; d < DEE; d++)
            if (dmap_ext[d * NEE + n] > 0.5f) del = d;
        float xs = Xext[(size_t)del * BB * NEE + b * NEE + n];
        if (xs > 0.5f) atomicOr(&g_mask_ext[n], 1u << b);
    }
}

// ---------------------------------------------------------------------------
// Kernel 2: compaction into ONE combined offset list per batch.
// Entries are 64-bit byte offsets relative to W_int. After the masks are
// consumed, blocks 0..31 cooperatively re-zero them for the next call.
// ---------------------------------------------------------------------------
__global__ void __launch_bounds__(256) k_compact(const float* __restrict__ W_int,
                                                 const float* __restrict__ W_ext) {
    int b = blockIdx.x;            // 0..31
    int tid = threadIdx.x;
    int w = tid >> 5, lane = tid & 31;
    unsigned lt = (lane == 0) ? 0u : (0xffffffffu >> (32 - lane));

    const long long ext_base = (long long)((const char*)W_ext - (const char*)W_int);
    const long long zero_off = (long long)((const char*)g_zero - (const char*)W_int);

    __shared__ int wcnt[8], wbase[8], s_total, s_base_ext;

    // ---- internal ----
    {
        int cnt = 0;
#pragma unroll
        for (int r = 0; r < 16; r++) {
            int i = (w * 16 + r) * 32 + lane;
            bool act = (g_mask_int[i] >> b) & 1u;
            cnt += __popc(__ballot_sync(0xffffffffu, act));
        }
        if (lane == 0) wcnt[w] = cnt;
        __syncthreads();
        if (tid == 0) {
            int s = 0;
#pragma unroll
            for (int j = 0; j < 8; j++) { wbase[j] = s; s += wcnt[j]; }
            s_total = s;
            s_base_ext = s;
        }
        __syncthreads();
        int base = wbase[w];
#pragma unroll
        for (int r = 0; r < 16; r++) {
            int i = (w * 16 + r) * 32 + lane;
            bool act = (g_mask_int[i] >> b) & 1u;
            unsigned bal = __ballot_sync(0xffffffffu, act);
            if (act) g_list[b][base + __popc(bal & lt)] = (long long)i * (NN * 4);
            base += __popc(bal);
        }
        __syncthreads();
    }

    // ---- external (appended) ----
    {
        int cnt = 0;
#pragma unroll
        for (int r = 0; r < 8; r++) {
            int i = (w * 8 + r) * 32 + lane;
            bool act = (g_mask_ext[i] >> b) & 1u;
            cnt += __popc(__ballot_sync(0xffffffffu, act));
        }
        if (lane == 0) wcnt[w] = cnt;
        __syncthreads();
        if (tid == 0) {
            int s = s_base_ext;
#pragma unroll
            for (int j = 0; j < 8; j++) { wbase[j] = s; s += wcnt[j]; }
            s_total = s;
        }
        __syncthreads();
        int base = wbase[w];
#pragma unroll
        for (int r = 0; r < 8; r++) {
            int i = (w * 8 + r) * 32 + lane;
            bool act = (g_mask_ext[i] >> b) & 1u;
            unsigned bal = __ballot_sync(0xffffffffu, act);
            if (act) g_list[b][base + __popc(bal & lt)] = ext_base + (long long)i * (NN * 4);
            base += __popc(bal);
        }
        __syncthreads();
        int t = s_total;
        int padded = (t + 15) & ~15;
        if (t + tid < padded) g_list[b][t + tid] = zero_off;
        if (tid == 0) g_cnt[b] = padded;
    }

    // ---- re-zero masks for the next call (each block owns a 1/32 slice) ----
    __syncthreads();
    {
        int per = NN / BB;            // 128
        int i0 = b * per;
        if (tid < per) g_mask_int[i0 + tid] = 0u;
        int per_e = NEE / BB;         // 64
        int j0 = b * per_e;
        if (tid < per_e) g_mask_ext[j0 + tid] = 0u;
    }
}

// ---------------------------------------------------------------------------
// Kernel 3: split-K sparse row-gather, float2 per thread (unchanged - proven).
// ---------------------------------------------------------------------------
__global__ void k_gather(const float* __restrict__ W_int,
                         float* __restrict__ out) {
    const int b = blockIdx.y;
    const int s = blockIdx.z;
    const int nwin = g_cnt[b] >> 4;
    const long long* __restrict__ lst = g_list[b];

    const int n2 = (blockIdx.x * 128 + threadIdx.x) * 2;  // column pair
    const char* base = (const char*)W_int + (size_t)n2 * 4;

    float ax0 = 0.f, ay0 = 0.f, ax1 = 0.f, ay1 = 0.f;
    float ax2 = 0.f, ay2 = 0.f, ax3 = 0.f, ay3 = 0.f;

    for (int j = s; j < nwin; j += NSPLIT) {
        const int k = j * 16;
        long long o[16];
#pragma unroll
        for (int u = 0; u < 16; u++) o[u] = __ldg(lst + k + u);
        float2 w[16];
#pragma unroll
        for (int u = 0; u < 16; u++)
            w[u] = __ldg((const float2*)(base + o[u]));
#pragma unroll
        for (int u = 0; u < 16; u += 4) {
            ax0 += w[u].x;     ay0 += w[u].y;
            ax1 += w[u + 1].x; ay1 += w[u + 1].y;
            ax2 += w[u + 2].x; ay2 += w[u + 2].y;
            ax3 += w[u + 3].x; ay3 += w[u + 3].y;
        }
    }

    float2 r;
    r.x = (ax0 + ax1) + (ax2 + ax3);
    r.y = (ay0 + ay1) + (ay2 + ay3);
    *(float2*)(&g_part[s][b][n2]) = r;
}

// ---------------------------------------------------------------------------
// Kernel 4: combine partials + leak/reset -> V_new (row 1). float4: each
// thread handles 4 columns -> 6x LDG.128 + 1x STG.128, fixed summation order.
// ---------------------------------------------------------------------------
__global__ void k_combine(const float* __restrict__ V, float* __restrict__ out) {
    int t = blockIdx.x * blockDim.x + threadIdx.x;     // 0 .. B*N/4-1
    int idx = t * 4;
    int b = idx >> 12;
    int n = idx & (NN - 1);

    float4 x  = *(const float4*)(out + idx);            // X (row 0)
    float4 v  = *(const float4*)(V + idx);
    float4 p0 = *(const float4*)(&g_part[0][b][n]);
    float4 p1 = *(const float4*)(&g_part[1][b][n]);
    float4 p2 = *(const float4*)(&g_part[2][b][n]);
    float4 p3 = *(const float4*)(&g_part[3][b][n]);

    float4 r;
    r.x = 0.95f * v.x * (1.0f - x.x) + p0.x + p1.x + p2.x + p3.x;
    r.y = 0.95f * v.y * (1.0f - x.y) + p0.y + p1.y + p2.y + p3.y;
    r.z = 0.95f * v.z * (1.0f - x.z) + p0.z + p1.z + p2.z + p3.z;
    r.w = 0.95f * v.w * (1.0f - x.w) + p0.w + p1.w + p2.w + p3.w;

    *(float4*)(out + BB * NN + idx) = r;                // row 1: V_new
}

// ---------------------------------------------------------------------------
extern "C" void kernel_launch(void* const* d_in, const int* in_sizes, int n_in,
                              void* d_out, int out_size) {
    const float* V        = (const float*)d_in[0];   // [B,N]
    const float* a        = (const float*)d_in[1];   // [B,N]
    const float* Xd       = (const float*)d_in[2];   // [D,B,N]
    const float* Xext     = (const float*)d_in[3];   // [DE,B,NE]
    const float* W_int    = (const float*)d_in[4];   // [N,N]
    const float* W_ext    = (const float*)d_in[5];   // [NE,N]
    const float* dmap_int = (const float*)d_in[6];   // [D,N]
    const float* dmap_ext = (const float*)d_in[7];   // [DE,NE]
    float* out = (float*)d_out;                      // [3,B,N]

    k_spikemask<<<(BB * NN) / 256, 256>>>(V, a, Xd, Xext, dmap_int, dmap_ext, out);
    k_compact<<<BB, 256>>>(W_int, W_ext);
    dim3 grid(NN / 256, BB, NSPLIT);
    k_gather<<<grid, 128>>>(W_int, out);
    k_combine<<<(BB * NN) / 1024, 256>>>(V, out);
}

// round 13
// speedup vs baseline: 1.3268x; 1.3268x over previous
#include <cuda_runtime.h>

// Problem shapes (fixed)
#define BB 32
#define NN 4096
#define DD 8
#define NEE 2048
#define DEE 4
#define NSPLIT 4

// Device scratch (static globals; no allocation). Zero-initialized at module
// load; every kernel_launch call leaves masks zeroed again (k_combine tail),
// so the sequence is deterministic call-to-call.
__device__ unsigned g_mask_int[NN];
__device__ unsigned g_mask_ext[NEE];
__device__ long long g_list[BB][6784];   // premultiplied byte offsets rel. W_int
__device__ int g_cnt[BB];                // padded combined length (multiple of 16)
__device__ float g_part[NSPLIT][BB][NN]; // split-K partial sums
__device__ float g_zero[NN];             // stays all-zero; pad rows point here

// ---------------------------------------------------------------------------
// Kernel 1 (fused spike + mask): thread per (b,n).
// ---------------------------------------------------------------------------
__global__ void k_spikemask(const float* __restrict__ V, const float* __restrict__ a,
                            const float* __restrict__ Xd, const float* __restrict__ Xext,
                            const float* __restrict__ dmap_int,
                            const float* __restrict__ dmap_ext,
                            float* __restrict__ out) {
    int idx = blockIdx.x * blockDim.x + threadIdx.x;   // 0 .. B*N-1
    int b = idx >> 12;                                 // idx / NN
    int n = idx & (NN - 1);

    float v  = V[idx];
    float aa = a[idx];
    float th = __fadd_rn(1.0f, __fmul_rn(1.8f, aa));
    float x  = (__fadd_rn(v, -th) >= 0.0f) ? 1.0f : 0.0f;
    out[idx] = x;                                       // row 0: X
    out[2 * BB * NN + idx] = 0.98f * aa + x;            // row 2: a_new

    // internal source (b, n)
    {
        int del = 0;
#pragma unroll
        for (int d = 0; d < DD; d++)
            if (dmap_int[d * NN + n] > 0.5f) del = d;
        float xs = (del == 0) ? x : Xd[(size_t)(del - 1) * BB * NN + idx];
        if (xs > 0.5f) atomicOr(&g_mask_int[n], 1u << b);
    }
    // external source (b, n) for n < NE
    if (n < NEE) {
        int del = 0;
#pragma unroll
        for (int d = 0; d < DEE; d++)
            if (dmap_ext[d * NEE + n] > 0.5f) del = d;
        float xs = Xext[(size_t)del * BB * NEE + b * NEE + n];
        if (xs > 0.5f) atomicOr(&g_mask_ext[n], 1u << b);
    }
}

// ---------------------------------------------------------------------------
// Kernel 2: compaction into ONE combined offset list per batch.
// Entries are 64-bit byte offsets relative to W_int:
//   internal i -> i*N*4 ; external j -> (W_ext - W_int) + j*N*4 ;
//   padding    -> (g_zero - W_int)  (loads read zeros; no predicates needed).
// Padded to a multiple of 16.
// ---------------------------------------------------------------------------
__global__ void __launch_bounds__(256) k_compact(const float* __restrict__ W_int,
                                                 const float* __restrict__ W_ext) {
    int b = blockIdx.x;            // 0..31
    int tid = threadIdx.x;
    int w = tid >> 5, lane = tid & 31;
    unsigned lt = (lane == 0) ? 0u : (0xffffffffu >> (32 - lane));

    const long long ext_base = (long long)((const char*)W_ext - (const char*)W_int);
    const long long zero_off = (long long)((const char*)g_zero - (const char*)W_int);

    __shared__ int wcnt[8], wbase[8], s_total, s_base_ext;

    // ---- internal ----
    {
        int cnt = 0;
#pragma unroll
        for (int r = 0; r < 16; r++) {
            int i = (w * 16 + r) * 32 + lane;
            bool act = (g_mask_int[i] >> b) & 1u;
            cnt += __popc(__ballot_sync(0xffffffffu, act));
        }
        if (lane == 0) wcnt[w] = cnt;
        __syncthreads();
        if (tid == 0) {
            int s = 0;
#pragma unroll
            for (int j = 0; j < 8; j++) { wbase[j] = s; s += wcnt[j]; }
            s_total = s;
            s_base_ext = s;
        }
        __syncthreads();
        int base = wbase[w];
#pragma unroll
        for (int r = 0; r < 16; r++) {
            int i = (w * 16 + r) * 32 + lane;
            bool act = (g_mask_int[i] >> b) & 1u;
            unsigned bal = __ballot_sync(0xffffffffu, act);
            if (act) g_list[b][base + __popc(bal & lt)] = (long long)i * (NN * 4);
            base += __popc(bal);
        }
        __syncthreads();
    }

    // ---- external (appended) ----
    {
        int cnt = 0;
#pragma unroll
        for (int r = 0; r < 8; r++) {
            int i = (w * 8 + r) * 32 + lane;
            bool act = (g_mask_ext[i] >> b) & 1u;
            cnt += __popc(__ballot_sync(0xffffffffu, act));
        }
        if (lane == 0) wcnt[w] = cnt;
        __syncthreads();
        if (tid == 0) {
            int s = s_base_ext;
#pragma unroll
            for (int j = 0; j < 8; j++) { wbase[j] = s; s += wcnt[j]; }
            s_total = s;
        }
        __syncthreads();
        int base = wbase[w];
#pragma unroll
        for (int r = 0; r < 8; r++) {
            int i = (w * 8 + r) * 32 + lane;
            bool act = (g_mask_ext[i] >> b) & 1u;
            unsigned bal = __ballot_sync(0xffffffffu, act);
            if (act) g_list[b][base + __popc(bal & lt)] = ext_base + (long long)i * (NN * 4);
            base += __popc(bal);
        }
        __syncthreads();
        int t = s_total;
        int padded = (t + 15) & ~15;
        if (t + tid < padded) g_list[b][t + tid] = zero_off;
        if (tid == 0) g_cnt[b] = padded;
    }
}

// ---------------------------------------------------------------------------
// Kernel 3: split-K sparse row-gather, float2 per thread.
// grid (N/256, B, NSPLIT), 128 threads. Inner step per source:
//   LDG.64 offset (warp-uniform, L1-hot) -> 64-bit add -> LDG.64 W -> 2 FADD.
// No compares/selects/IMAD.WIDE. Partials to g_part (fixed-order combine).
// ---------------------------------------------------------------------------
__global__ void k_gather(const float* __restrict__ W_int,
                         float* __restrict__ out) {
    const int b = blockIdx.y;
    const int s = blockIdx.z;
    const int nwin = g_cnt[b] >> 4;
    const long long* __restrict__ lst = g_list[b];

    const int n2 = (blockIdx.x * 128 + threadIdx.x) * 2;  // column pair
    const char* base = (const char*)W_int + (size_t)n2 * 4;

    float ax0 = 0.f, ay0 = 0.f, ax1 = 0.f, ay1 = 0.f;
    float ax2 = 0.f, ay2 = 0.f, ax3 = 0.f, ay3 = 0.f;

    for (int j = s; j < nwin; j += NSPLIT) {
        const int k = j * 16;
        long long o[16];
#pragma unroll
        for (int u = 0; u < 16; u++) o[u] = __ldg(lst + k + u);
        float2 w[16];
#pragma unroll
        for (int u = 0; u < 16; u++)
            w[u] = __ldg((const float2*)(base + o[u]));
#pragma unroll
        for (int u = 0; u < 16; u += 4) {
            ax0 += w[u].x;     ay0 += w[u].y;
            ax1 += w[u + 1].x; ay1 += w[u + 1].y;
            ax2 += w[u + 2].x; ay2 += w[u + 2].y;
            ax3 += w[u + 3].x; ay3 += w[u + 3].y;
        }
    }

    float2 r;
    r.x = (ax0 + ax1) + (ax2 + ax3);
    r.y = (ay0 + ay1) + (ay2 + ay3);
    *(float2*)(&g_part[s][b][n2]) = r;
}

// ---------------------------------------------------------------------------
// Kernel 4: combine partials + leak/reset -> V_new (row 1), fixed order.
// Scalar, one element per thread (max thread count = max MLP for this
// latency-bound kernel). Also re-zeroes the masks for the next call.
// ---------------------------------------------------------------------------
__global__ void k_combine(const float* __restrict__ V, float* __restrict__ out) {
    int idx = blockIdx.x * blockDim.x + threadIdx.x;   // 0 .. B*N-1
    int b = idx >> 12;
    int n = idx & (NN - 1);
    float x = out[idx];                                 // X (row 0)
    float acc = 0.95f * V[idx] * (1.0f - x);
    acc += g_part[0][b][n];
    acc += g_part[1][b][n];
    acc += g_part[2][b][n];
    acc += g_part[3][b][n];
    out[BB * NN + idx] = acc;                           // row 1: V_new

    if (idx < NN)  g_mask_int[idx] = 0u;
    if (idx < NEE) g_mask_ext[idx] = 0u;
}

// ---------------------------------------------------------------------------
extern "C" void kernel_launch(void* const* d_in, const int* in_sizes, int n_in,
                              void* d_out, int out_size) {
    const float* V        = (const float*)d_in[0];   // [B,N]
    const float* a        = (const float*)d_in[1];   // [B,N]
    const float* Xd       = (const float*)d_in[2];   // [D,B,N]
    const float* Xext     = (const float*)d_in[3];   // [DE,B,NE]
    const float* W_int    = (const float*)d_in[4];   // [N,N]
    const float* W_ext    = (const float*)d_in[5];   // [NE,N]
    const float* dmap_int = (const float*)d_in[6];   // [D,N]
    const float* dmap_ext = (const float*)d_in[7];   // [DE,NE]
    float* out = (float*)d_out;                      // [3,B,N]

    k_spikemask<<<(BB * NN) / 256, 256>>>(V, a, Xd, Xext, dmap_int, dmap_ext, out);
    k_compact<<<BB, 256>>>(W_int, W_ext);
    dim3 grid(NN / 256, BB, NSPLIT);
    k_gather<<<grid, 128>>>(W_int, out);
    k_combine<<<(BB * NN) / 256, 256>>>(V, out);
}

// round 14
// speedup vs baseline: 1.4076x; 1.0609x over previous
#include <cuda_runtime.h>

// Problem shapes (fixed)
#define BB 32
#define NN 4096
#define DD 8
#define NEE 2048
#define DEE 4
#define NSPLIT 8

// Device scratch (static globals; no allocation). Zero-initialized at module
// load; every kernel_launch call leaves masks zeroed again (k_combine tail),
// so the sequence is deterministic call-to-call.
__device__ unsigned g_mask_int[NN];
__device__ unsigned g_mask_ext[NEE];
__device__ long long g_list[BB][6784];   // premultiplied byte offsets rel. W_int
__device__ int g_cnt[BB];                // padded combined length (multiple of 16)
__device__ float g_part[NSPLIT][BB][NN]; // split-K partial sums
__device__ float g_zero[NN];             // stays all-zero; pad rows point here

// ---------------------------------------------------------------------------
// Kernel 1 (fused spike + mask): thread per (b,n).
// ---------------------------------------------------------------------------
__global__ void k_spikemask(const float* __restrict__ V, const float* __restrict__ a,
                            const float* __restrict__ Xd, const float* __restrict__ Xext,
                            const float* __restrict__ dmap_int,
                            const float* __restrict__ dmap_ext,
                            float* __restrict__ out) {
    int idx = blockIdx.x * blockDim.x + threadIdx.x;   // 0 .. B*N-1
    int b = idx >> 12;                                 // idx / NN
    int n = idx & (NN - 1);

    float v  = V[idx];
    float aa = a[idx];
    float th = __fadd_rn(1.0f, __fmul_rn(1.8f, aa));
    float x  = (__fadd_rn(v, -th) >= 0.0f) ? 1.0f : 0.0f;
    out[idx] = x;                                       // row 0: X
    out[2 * BB * NN + idx] = 0.98f * aa + x;            // row 2: a_new

    // internal source (b, n)
    {
        int del = 0;
#pragma unroll
        for (int d = 0; d < DD; d++)
            if (dmap_int[d * NN + n] > 0.5f) del = d;
        float xs = (del == 0) ? x : Xd[(size_t)(del - 1) * BB * NN + idx];
        if (xs > 0.5f) atomicOr(&g_mask_int[n], 1u << b);
    }
    // external source (b, n) for n < NE
    if (n < NEE) {
        int del = 0;
#pragma unroll
        for (int d = 0; d < DEE; d++)
            if (dmap_ext[d * NEE + n] > 0.5f) del = d;
        float xs = Xext[(size_t)del * BB * NEE + b * NEE + n];
        if (xs > 0.5f) atomicOr(&g_mask_ext[n], 1u << b);
    }
}

// ---------------------------------------------------------------------------
// Kernel 2: compaction into ONE combined offset list per batch.
// Entries are 64-bit byte offsets relative to W_int:
//   internal i -> i*N*4 ; external j -> (W_ext - W_int) + j*N*4 ;
//   padding    -> (g_zero - W_int)  (loads read zeros; no predicates needed).
// Padded to a multiple of 16.
// ---------------------------------------------------------------------------
__global__ void __launch_bounds__(256) k_compact(const float* __restrict__ W_int,
                                                 const float* __restrict__ W_ext) {
    int b = blockIdx.x;            // 0..31
    int tid = threadIdx.x;
    int w = tid >> 5, lane = tid & 31;
    unsigned lt = (lane == 0) ? 0u : (0xffffffffu >> (32 - lane));

    const long long ext_base = (long long)((const char*)W_ext - (const char*)W_int);
    const long long zero_off = (long long)((const char*)g_zero - (const char*)W_int);

    __shared__ int wcnt[8], wbase[8], s_total, s_base_ext;

    // ---- internal ----
    {
        int cnt = 0;
#pragma unroll
        for (int r = 0; r < 16; r++) {
            int i = (w * 16 + r) * 32 + lane;
            bool act = (g_mask_int[i] >> b) & 1u;
            cnt += __popc(__ballot_sync(0xffffffffu, act));
        }
        if (lane == 0) wcnt[w] = cnt;
        __syncthreads();
        if (tid == 0) {
            int s = 0;
#pragma unroll
            for (int j = 0; j < 8; j++) { wbase[j] = s; s += wcnt[j]; }
            s_total = s;
            s_base_ext = s;
        }
        __syncthreads();
        int base = wbase[w];
#pragma unroll
        for (int r = 0; r < 16; r++) {
            int i = (w * 16 + r) * 32 + lane;
            bool act = (g_mask_int[i] >> b) & 1u;
            unsigned bal = __ballot_sync(0xffffffffu, act);
            if (act) g_list[b][base + __popc(bal & lt)] = (long long)i * (NN * 4);
            base += __popc(bal);
        }
        __syncthreads();
    }

    // ---- external (appended) ----
    {
        int cnt = 0;
#pragma unroll
        for (int r = 0; r < 8; r++) {
            int i = (w * 8 + r) * 32 + lane;
            bool act = (g_mask_ext[i] >> b) & 1u;
            cnt += __popc(__ballot_sync(0xffffffffu, act));
        }
        if (lane == 0) wcnt[w] = cnt;
        __syncthreads();
        if (tid == 0) {
            int s = s_base_ext;
#pragma unroll
            for (int j = 0; j < 8; j++) { wbase[j] = s; s += wcnt[j]; }
            s_total = s;
        }
        __syncthreads();
        int base = wbase[w];
#pragma unroll
        for (int r = 0; r < 8; r++) {
            int i = (w * 8 + r) * 32 + lane;
            bool act = (g_mask_ext[i] >> b) & 1u;
            unsigned bal = __ballot_sync(0xffffffffu, act);
            if (act) g_list[b][base + __popc(bal & lt)] = ext_base + (long long)i * (NN * 4);
            base += __popc(bal);
        }
        __syncthreads();
        int t = s_total;
        int padded = (t + 15) & ~15;
        if (t + tid < padded) g_list[b][t + tid] = zero_off;
        if (tid == 0) g_cnt[b] = padded;
    }
}

// ---------------------------------------------------------------------------
// Kernel 3: split-K sparse row-gather, float2 per thread (body unchanged -
// proven). NSPLIT=8 -> grid (16, 32, 8) = 4096 blocks for full warp
// residency and tighter tail balance (2-3 windows per split).
// ---------------------------------------------------------------------------
__global__ void k_gather(const float* __restrict__ W_int,
                         float* __restrict__ out) {
    const int b = blockIdx.y;
    const int s = blockIdx.z;
    const int nwin = g_cnt[b] >> 4;
    const long long* __restrict__ lst = g_list[b];

    const int n2 = (blockIdx.x * 128 + threadIdx.x) * 2;  // column pair
    const char* base = (const char*)W_int + (size_t)n2 * 4;

    float ax0 = 0.f, ay0 = 0.f, ax1 = 0.f, ay1 = 0.f;
    float ax2 = 0.f, ay2 = 0.f, ax3 = 0.f, ay3 = 0.f;

    for (int j = s; j < nwin; j += NSPLIT) {
        const int k = j * 16;
        long long o[16];
#pragma unroll
        for (int u = 0; u < 16; u++) o[u] = __ldg(lst + k + u);
        float2 w[16];
#pragma unroll
        for (int u = 0; u < 16; u++)
            w[u] = __ldg((const float2*)(base + o[u]));
#pragma unroll
        for (int u = 0; u < 16; u += 4) {
            ax0 += w[u].x;     ay0 += w[u].y;
            ax1 += w[u + 1].x; ay1 += w[u + 1].y;
            ax2 += w[u + 2].x; ay2 += w[u + 2].y;
            ax3 += w[u + 3].x; ay3 += w[u + 3].y;
        }
    }

    float2 r;
    r.x = (ax0 + ax1) + (ax2 + ax3);
    r.y = (ay0 + ay1) + (ay2 + ay3);
    *(float2*)(&g_part[s][b][n2]) = r;
}

// ---------------------------------------------------------------------------
// Kernel 4: combine partials + leak/reset -> V_new (row 1), fixed order.
// Scalar, one element per thread (max thread count = max MLP for this
// latency-bound kernel). Also re-zeroes the masks for the next call.
// ---------------------------------------------------------------------------
__global__ void k_combine(const float* __restrict__ V, float* __restrict__ out) {
    int idx = blockIdx.x * blockDim.x + threadIdx.x;   // 0 .. B*N-1
    int b = idx >> 12;
    int n = idx & (NN - 1);
    float x = out[idx];                                 // X (row 0)
    float acc = 0.95f * V[idx] * (1.0f - x);
    acc += g_part[0][b][n];
    acc += g_part[1][b][n];
    acc += g_part[2][b][n];
    acc += g_part[3][b][n];
    acc += g_part[4][b][n];
    acc += g_part[5][b][n];
    acc += g_part[6][b][n];
    acc += g_part[7][b][n];
    out[BB * NN + idx] = acc;                           // row 1: V_new

    if (idx < NN)  g_mask_int[idx] = 0u;
    if (idx < NEE) g_mask_ext[idx] = 0u;
}

// ---------------------------------------------------------------------------
extern "C" void kernel_launch(void* const* d_in, const int* in_sizes, int n_in,
                              void* d_out, int out_size) {
    const float* V        = (const float*)d_in[0];   // [B,N]
    const float* a        = (const float*)d_in[1];   // [B,N]
    const float* Xd       = (const float*)d_in[2];   // [D,B,N]
    const float* Xext     = (const float*)d_in[3];   // [DE,B,NE]
    const float* W_int    = (const float*)d_in[4];   // [N,N]
    const float* W_ext    = (const float*)d_in[5];   // [NE,N]
    const float* dmap_int = (const float*)d_in[6];   // [D,N]
    const float* dmap_ext = (const float*)d_in[7];   // [DE,NE]
    float* out = (float*)d_out;                      // [3,B,N]

    k_spikemask<<<(BB * NN) / 256, 256>>>(V, a, Xd, Xext, dmap_int, dmap_ext, out);
    k_compact<<<BB, 256>>>(W_int, W_ext);
    dim3 grid(NN / 256, BB, NSPLIT);
    k_gather<<<grid, 128>>>(W_int, out);
    k_combine<<<(BB * NN) / 256, 256>>>(V, out);
}